// round 3
// baseline (speedup 1.0000x reference)
#include <cuda_runtime.h>

#define N_ORB 256
#define NF    128
#define S     132          // padded row stride (floats); 16B-aligned rows, conflict-free
#define BATCH 4096
#define NTHREADS 256

__global__ __launch_bounds__(NTHREADS)
void slater_logdet_kernel(const int* __restrict__ n_occ,
                          const float* __restrict__ M,
                          float* __restrict__ out)
{
    extern __shared__ float As[];            // NF * S floats
    __shared__ int      Rsh[NF];
    __shared__ int      warpCnt[8];
    __shared__ unsigned s_k[8];

    const int b    = blockIdx.x;
    const int tid  = threadIdx.x;
    const int lane = tid & 31;
    const int wid  = tid >> 5;
    const int j    = tid & 127;              // column owned in trailing update
    const int half = tid >> 7;               // row-interleave selector

    // ---- Phase 1: occupied orbital indices, ascending (ballot + scan) ----
    int occ = (n_occ[b * N_ORB + tid] != 0);
    unsigned bm = __ballot_sync(0xffffffffu, occ);
    int rank = __popc(bm & ((1u << lane) - 1u));
    if (lane == 0) warpCnt[wid] = __popc(bm);
    __syncthreads();
    int base = 0;
    #pragma unroll
    for (int w = 0; w < 8; w++) if (w < wid) base += warpCnt[w];
    if (occ) Rsh[base + rank] = tid;
    __syncthreads();

    // ---- Phase 2: gather A[f][:] = M[R[f]][:]  (float4) ----
    const float4* M4 = (const float4*)M;
    #pragma unroll
    for (int t = 0; t < 16; t++) {
        int idx = tid + t * NTHREADS;        // 0 .. 4095
        int f = idx >> 5;
        int q = idx & 31;
        float4 v = M4[Rsh[f] * 32 + q];
        *(float4*)&As[f * S + 4 * q] = v;
    }
    __syncthreads();

    // ---- Phase 3: LU with partial pivoting; log|det| = sum log|pivot| ----
    float logabs = 0.0f;                     // maintained redundantly by ALL threads

    for (int k = 0; k < NF; k++) {
        // pivot argmax over rows >= k of |A[i][k]|, via packed key:
        // top 25 bits = fabs float bits (monotone), low 7 bits = row index.
        unsigned key = 0u;
        if (half == 0 && tid >= k) {
            float av = fabsf(As[tid * S + k]);
            key = (__float_as_uint(av) & 0xFFFFFF80u) | (unsigned)tid;
        }
        unsigned wmax = __reduce_max_sync(0xffffffffu, key);
        if (lane == 0) s_k[wid] = wmax;
        __syncthreads();

        unsigned kmax = 0u;
        #pragma unroll
        for (int w = 0; w < 8; w++) kmax = max(kmax, s_k[w]);
        const int   p     = (int)(kmax & 127u);
        const float pivot = As[p * S + k];   // broadcast read, pre-swap

        logabs += logf(fabsf(pivot));
        const float inv = 1.0f / pivot;
        __syncthreads();                     // pivot reads complete before swap writes

        // row swap k <-> p (threads 0..127, one column each)
        if (p != k && half == 0) {
            float a = As[k * S + tid];
            float c = As[p * S + tid];
            As[k * S + tid] = c;
            As[p * S + tid] = a;
        }
        __syncthreads();

        // trailing update: A[i][j] -= A[i][k] * (inv * A[k][j]),  i>k, j>k
        if (j > k) {
            const float c = inv * As[k * S + j];
            for (int i = k + 1 + half; i < NF; i += 2) {
                As[i * S + j] -= As[i * S + k] * c;
            }
        }
        __syncthreads();
    }

    if (tid == 0) {
        out[b] = logabs;                     // output dtype: float32 (real part only)
    }
}

extern "C" void kernel_launch(void* const* d_in, const int* in_sizes, int n_in,
                              void* d_out, int out_size)
{
    (void)in_sizes; (void)n_in; (void)out_size;
    const int*   n_occ = (const int*)d_in[0];
    const float* M     = (const float*)d_in[1];
    float*       out   = (float*)d_out;

    const int smem = NF * S * (int)sizeof(float);   // 67584 bytes
    cudaFuncSetAttribute(slater_logdet_kernel,
                         cudaFuncAttributeMaxDynamicSharedMemorySize, smem);
    slater_logdet_kernel<<<BATCH, NTHREADS, smem>>>(n_occ, M, out);
}

// round 4
// speedup vs baseline: 2.2412x; 2.2412x over previous
#include <cuda_runtime.h>

#define N_ORB 256
#define NF    128
#define S     132          // padded row stride (floats); rows 16B-aligned, conflict-free
#define NB    8            // panel width
#define BATCH 4096
#define NTHREADS 256

__global__ __launch_bounds__(NTHREADS)
void slater_logdet_kernel(const int* __restrict__ n_occ,
                          const float* __restrict__ M,
                          float* __restrict__ out)
{
    extern __shared__ float As[];            // NF * S floats
    __shared__ int      Rsh[NF];
    __shared__ int      warpCnt[8];
    __shared__ unsigned s_k[8];
    __shared__ float    s_inv[NB];

    const int b    = blockIdx.x;
    const int tid  = threadIdx.x;
    const int lane = tid & 31;
    const int wid  = tid >> 5;

    // ---- Phase 1: occupied orbital indices, ascending (ballot + scan) ----
    int occ = (n_occ[b * N_ORB + tid] != 0);
    unsigned bm = __ballot_sync(0xffffffffu, occ);
    int rank = __popc(bm & ((1u << lane) - 1u));
    if (lane == 0) warpCnt[wid] = __popc(bm);
    __syncthreads();
    int base = 0;
    #pragma unroll
    for (int w = 0; w < 8; w++) if (w < wid) base += warpCnt[w];
    if (occ) Rsh[base + rank] = tid;
    __syncthreads();

    // ---- Phase 2: gather A[f][:] = M[R[f]][:]  (float4) ----
    const float4* M4 = (const float4*)M;
    #pragma unroll
    for (int t = 0; t < 16; t++) {
        int idx = tid + t * NTHREADS;        // 0 .. 4095
        int f = idx >> 5;
        int q = idx & 31;
        float4 v = M4[Rsh[f] * 32 + q];
        *(float4*)&As[f * S + 4 * q] = v;
    }
    __syncthreads();

    // ---- Phase 3: blocked LU (NB-wide panels) with partial pivoting ----
    float logabs = 0.0f;                     // maintained redundantly by ALL threads

    for (int kb = 0; kb < NF; kb += NB) {
        // ---------- panel factorization (columns kb..kb+NB-1) ----------
        #pragma unroll 1
        for (int m = 0; m < NB; m++) {
            const int k = kb + m;
            // pivot argmax over rows >= k of |A[i][k]| (packed key)
            unsigned key = 0u;
            if (tid < NF && tid >= k) {
                float av = fabsf(As[tid * S + k]);
                key = (__float_as_uint(av) & 0xFFFFFF80u) | (unsigned)tid;
            }
            unsigned wmax = __reduce_max_sync(0xffffffffu, key);
            if (lane == 0) s_k[wid] = wmax;
            __syncthreads();

            unsigned kmax = 0u;
            #pragma unroll
            for (int w = 0; w < 8; w++) kmax = max(kmax, s_k[w]);
            const int   p     = (int)(kmax & 127u);
            const float pivot = As[p * S + k];

            logabs += logf(fabsf(pivot));
            const float inv = 1.0f / pivot;
            if (tid == 0) s_inv[m] = inv;
            __syncthreads();                 // pivot reads done before swap writes

            if (p != k && tid < NF) {        // full row swap k <-> p
                float a = As[k * S + tid];
                float c = As[p * S + tid];
                As[k * S + tid] = c;
                As[p * S + tid] = a;
            }
            __syncthreads();

            // narrow rank-1 update on remaining PANEL columns only (L stays raw)
            const int j = kb + (tid & 7);
            if (j > k) {
                const float c = inv * As[k * S + j];
                for (int i = k + 1 + (tid >> 3); i < NF; i += 32)
                    As[i * S + j] -= As[i * S + k] * c;
            }
            __syncthreads();
        }

        const int c0    = kb + NB;
        const int ncols = NF - c0;
        if (ncols > 0) {
            // ---------- triangular solve: V = diag(inv) * L11^{-1} * A12 ----------
            // stored in place of A12; GEMM then uses raw L21: A22 -= L21_raw * V.
            const int j = c0 + tid;
            if (j < NF) {
                float v[NB];
                #pragma unroll
                for (int m = 0; m < NB; m++) {
                    float a = As[(kb + m) * S + j];
                    #pragma unroll
                    for (int t = 0; t < m; t++)
                        a -= As[(kb + m) * S + (kb + t)] * v[t];   // raw L11, V has inv folded
                    v[m] = a * s_inv[m];
                }
                #pragma unroll
                for (int m = 0; m < NB; m++)
                    As[(kb + m) * S + j] = v[m];
            }
            __syncthreads();

            // ---------- GEMM: A22 -= L21_raw(128-c0 x 8) * V(8 x ncols) ----------
            const int nct    = ncols >> 2;           // 4-wide column tiles
            const int ntiles = nct * nct;            // square trailing block
            for (int t = tid; t < ntiles; t += NTHREADS) {
                const int tr = t / nct;
                const int tc = t - tr * nct;
                const int r0 = c0 + 4 * tr;
                const int j0 = c0 + 4 * tc;

                float l[4][8];
                #pragma unroll
                for (int r = 0; r < 4; r++) {
                    *(float4*)&l[r][0] = *(const float4*)&As[(r0 + r) * S + kb];
                    *(float4*)&l[r][4] = *(const float4*)&As[(r0 + r) * S + kb + 4];
                }
                float a[4][4];
                #pragma unroll
                for (int r = 0; r < 4; r++)
                    *(float4*)&a[r][0] = *(const float4*)&As[(r0 + r) * S + j0];

                #pragma unroll
                for (int m = 0; m < NB; m++) {
                    float u[4];
                    *(float4*)&u[0] = *(const float4*)&As[(kb + m) * S + j0];
                    #pragma unroll
                    for (int r = 0; r < 4; r++) {
                        a[r][0] -= l[r][m] * u[0];
                        a[r][1] -= l[r][m] * u[1];
                        a[r][2] -= l[r][m] * u[2];
                        a[r][3] -= l[r][m] * u[3];
                    }
                }
                #pragma unroll
                for (int r = 0; r < 4; r++)
                    *(float4*)&As[(r0 + r) * S + j0] = *(const float4*)&a[r][0];
            }
            __syncthreads();
        }
    }

    if (tid == 0) out[b] = logabs;
}

extern "C" void kernel_launch(void* const* d_in, const int* in_sizes, int n_in,
                              void* d_out, int out_size)
{
    (void)in_sizes; (void)n_in; (void)out_size;
    const int*   n_occ = (const int*)d_in[0];
    const float* M     = (const float*)d_in[1];
    float*       out   = (float*)d_out;

    const int smem = NF * S * (int)sizeof(float);   // 67584 bytes
    cudaFuncSetAttribute(slater_logdet_kernel,
                         cudaFuncAttributeMaxDynamicSharedMemorySize, smem);
    slater_logdet_kernel<<<BATCH, NTHREADS, smem>>>(n_occ, M, out);
}

// round 5
// speedup vs baseline: 2.3323x; 1.0406x over previous
#include <cuda_runtime.h>

#define N_ORB 256
#define NF    128
#define S     132          // padded row stride (floats); rows 16B-aligned
#define NB    8            // panel width
#define BATCH 4096
#define NTHREADS 256

__global__ __launch_bounds__(NTHREADS, 3)
void slater_logdet_kernel(const int* __restrict__ n_occ,
                          const float* __restrict__ M,
                          float* __restrict__ out)
{
    extern __shared__ float As[];            // NF * S floats
    __shared__ int   Rsh[NF];
    __shared__ int   warpCnt[8];
    __shared__ int   perm[NF];               // logical row -> physical row
    __shared__ int   rowoff[NF];             // perm[i] * S (refreshed per panel)
    __shared__ int   s_prow[NB];             // perm[kb+m] * S
    __shared__ float s_inv[NB];
    __shared__ float s_piv[NF];              // all 128 pivots
    __shared__ float s_red[8];

    const int b    = blockIdx.x;
    const int tid  = threadIdx.x;
    const int lane = tid & 31;
    const int wid  = tid >> 5;

    // ---- Phase 1: occupied orbital indices, ascending (ballot + scan) ----
    int occ = (n_occ[b * N_ORB + tid] != 0);
    unsigned bm = __ballot_sync(0xffffffffu, occ);
    int rank = __popc(bm & ((1u << lane) - 1u));
    if (lane == 0) warpCnt[wid] = __popc(bm);
    if (tid < NF) { perm[tid] = tid; rowoff[tid] = tid * S; }
    __syncthreads();
    int base = 0;
    #pragma unroll
    for (int w = 0; w < 8; w++) if (w < wid) base += warpCnt[w];
    if (occ) Rsh[base + rank] = tid;
    __syncthreads();

    // ---- Phase 2: gather A[f][:] = M[R[f]][:]  (float4) ----
    const float4* M4 = (const float4*)M;
    #pragma unroll
    for (int t = 0; t < 16; t++) {
        int idx = tid + t * NTHREADS;        // 0 .. 4095
        int f = idx >> 5;
        int q = idx & 31;
        float4 v = M4[Rsh[f] * 32 + q];
        *(float4*)&As[f * S + 4 * q] = v;
    }
    __syncthreads();

    // ---- Phase 3: blocked LU, panel in warp-0 registers, perm indirection ----
    for (int kb = 0; kb < NF; kb += NB) {

        // ---------- panel factorization: warp 0 only, in registers ----------
        if (wid == 0) {
            float a[4][8];                   // lane holds logical rows 4*lane..4*lane+3
            #pragma unroll
            for (int r = 0; r < 4; r++) {
                const int off = rowoff[4 * lane + r] + kb;
                *(float4*)&a[r][0] = *(const float4*)&As[off];
                *(float4*)&a[r][4] = *(const float4*)&As[off + 4];
            }
            #pragma unroll
            for (int m = 0; m < NB; m++) {
                const int k = kb + m;
                // argmax over rows >= k of |a[.][m]| (packed key: abs bits | row)
                unsigned key = 0u;
                #pragma unroll
                for (int r = 0; r < 4; r++) {
                    const int row = 4 * lane + r;
                    if (row >= k) {
                        unsigned kk = (__float_as_uint(fabsf(a[r][m])) & 0xFFFFFF80u)
                                      | (unsigned)row;
                        key = max(key, kk);
                    }
                }
                key = __reduce_max_sync(0xffffffffu, key);
                const int p  = (int)(key & 127u);
                const int tk = k >> 2, lk = k & 3;
                const int tp = p >> 2, lp = p & 3;

                // extract rows k and p (pre-swap values)
                float rowk[8], rowp[8];
                #pragma unroll
                for (int j = 0; j < 8; j++) {
                    float vk = a[0][j];
                    if (lk == 1) vk = a[1][j];
                    if (lk == 2) vk = a[2][j];
                    if (lk == 3) vk = a[3][j];
                    rowk[j] = __shfl_sync(0xffffffffu, vk, tk);
                    float vp = a[0][j];
                    if (lp == 1) vp = a[1][j];
                    if (lp == 2) vp = a[2][j];
                    if (lp == 3) vp = a[3][j];
                    rowp[j] = __shfl_sync(0xffffffffu, vp, tp);
                }
                const float pivot = rowp[m];
                const float inv   = 1.0f / pivot;

                // swap rows k <-> p in registers
                #pragma unroll
                for (int r = 0; r < 4; r++) {
                    const bool isk = (lane == tk) && (r == lk);
                    const bool isp = (lane == tp) && (r == lp);
                    #pragma unroll
                    for (int j = 0; j < 8; j++) {
                        if (isk)       a[r][j] = rowp[j];
                        else if (isp)  a[r][j] = rowk[j];
                    }
                }
                if (lane == 0) {
                    s_inv[m]  = inv;
                    s_piv[k]  = pivot;
                    if (p != k) { int t0 = perm[k]; perm[k] = perm[p]; perm[p] = t0; }
                }
                __syncwarp();

                // rank-1 update on remaining panel columns (L stays raw)
                float u[8];
                #pragma unroll
                for (int j = 0; j < 8; j++) u[j] = inv * rowp[j];
                #pragma unroll
                for (int r = 0; r < 4; r++) {
                    const int row = 4 * lane + r;
                    if (row > k) {
                        const float mult = a[r][m];
                        #pragma unroll
                        for (int j = 0; j < 8; j++)
                            if (j > m) a[r][j] -= mult * u[j];
                    }
                }
            }
            // write back panel (perm now final for this panel)
            #pragma unroll
            for (int r = 0; r < 4; r++) {
                const int off = perm[4 * lane + r] * S + kb;
                *(float4*)&As[off]     = *(float4*)&a[r][0];
                *(float4*)&As[off + 4] = *(float4*)&a[r][4];
            }
            if (lane < NB) s_prow[lane] = perm[kb + lane] * S;
        }
        __syncthreads();

        // refresh row offsets under the new permutation
        if (tid < NF) rowoff[tid] = perm[tid] * S;

        const int c0    = kb + NB;
        const int ncols = NF - c0;
        if (ncols > 0) {
            // ---------- trsm: V = diag(inv) * L11^{-1} * A12, in place ----------
            if (tid < ncols) {
                const int j = c0 + tid;
                float v[NB];
                #pragma unroll
                for (int m = 0; m < NB; m++) {
                    float acc = As[s_prow[m] + j];
                    #pragma unroll
                    for (int t2 = 0; t2 < m; t2++)
                        acc -= As[s_prow[m] + kb + t2] * v[t2];   // raw L11 (broadcast)
                    v[m] = acc * s_inv[m];
                }
                #pragma unroll
                for (int m = 0; m < NB; m++)
                    As[s_prow[m] + j] = v[m];
            }
            __syncthreads();

            // ---------- GEMM: A22 -= L21_raw * V  (division-free mapping) ----------
            const int nct = ncols >> 2;          // 4-wide column tiles (<= 30)
            const int tc  = tid & 31;            // column tile (warp lane)
            const int tr0 = tid >> 5;            // row tile start (warp-uniform)
            if (tc < nct) {
                const int j0 = c0 + 4 * tc;
                float uu[8][4];                  // hoisted U block for this column tile
                #pragma unroll
                for (int m = 0; m < NB; m++)
                    *(float4*)&uu[m][0] = *(const float4*)&As[s_prow[m] + j0];

                for (int tr = tr0; tr < nct; tr += 8) {
                    const int r0 = c0 + 4 * tr;
                    const int o0 = rowoff[r0],     o1 = rowoff[r0 + 1];
                    const int o2 = rowoff[r0 + 2], o3 = rowoff[r0 + 3];

                    float a0[4], a1[4], a2[4], a3[4];
                    *(float4*)a0 = *(const float4*)&As[o0 + j0];
                    *(float4*)a1 = *(const float4*)&As[o1 + j0];
                    *(float4*)a2 = *(const float4*)&As[o2 + j0];
                    *(float4*)a3 = *(const float4*)&As[o3 + j0];

                    #pragma unroll
                    for (int h = 0; h < 2; h++) {
                        float l0[4], l1[4], l2[4], l3[4];
                        *(float4*)l0 = *(const float4*)&As[o0 + kb + 4 * h];
                        *(float4*)l1 = *(const float4*)&As[o1 + kb + 4 * h];
                        *(float4*)l2 = *(const float4*)&As[o2 + kb + 4 * h];
                        *(float4*)l3 = *(const float4*)&As[o3 + kb + 4 * h];
                        #pragma unroll
                        for (int mm = 0; mm < 4; mm++) {
                            const int m = 4 * h + mm;
                            #pragma unroll
                            for (int c = 0; c < 4; c++) {
                                a0[c] -= l0[mm] * uu[m][c];
                                a1[c] -= l1[mm] * uu[m][c];
                                a2[c] -= l2[mm] * uu[m][c];
                                a3[c] -= l3[mm] * uu[m][c];
                            }
                        }
                    }
                    *(float4*)&As[o0 + j0] = *(float4*)a0;
                    *(float4*)&As[o1 + j0] = *(float4*)a1;
                    *(float4*)&As[o2 + j0] = *(float4*)a2;
                    *(float4*)&As[o3 + j0] = *(float4*)a3;
                }
            }
            __syncthreads();
        }
    }

    // ---- Phase 4: logabs = sum log|pivot|, parallel reduction ----
    float lsum = 0.0f;
    if (tid < NF) lsum = logf(fabsf(s_piv[tid]));
    #pragma unroll
    for (int o = 16; o; o >>= 1) lsum += __shfl_down_sync(0xffffffffu, lsum, o);
    if (lane == 0) s_red[wid] = lsum;
    __syncthreads();
    if (tid == 0) {
        float tot = 0.0f;
        #pragma unroll
        for (int w = 0; w < 8; w++) tot += s_red[w];
        out[b] = tot;
    }
}

extern "C" void kernel_launch(void* const* d_in, const int* in_sizes, int n_in,
                              void* d_out, int out_size)
{
    (void)in_sizes; (void)n_in; (void)out_size;
    const int*   n_occ = (const int*)d_in[0];
    const float* M     = (const float*)d_in[1];
    float*       out   = (float*)d_out;

    const int smem = NF * S * (int)sizeof(float);   // 67584 bytes dynamic
    cudaFuncSetAttribute(slater_logdet_kernel,
                         cudaFuncAttributeMaxDynamicSharedMemorySize, smem);
    slater_logdet_kernel<<<BATCH, NTHREADS, smem>>>(n_occ, M, out);
}

// round 6
// speedup vs baseline: 2.4435x; 1.0477x over previous
#include <cuda_runtime.h>

#define N_ORB 256
#define NF    128
#define S     132          // padded row stride (floats); rows 16B-aligned
#define NB    8            // panel width
#define BATCH 4096
#define NTHREADS 256

// Factor an NB-wide panel (cols kb..kb+NB-1, pivot over logical rows >= k)
// entirely inside one warp's registers. Lane holds logical rows 4*lane..4*lane+3.
// L stays raw (unscaled); pivots and reciprocals exported via s_piv / s_inv.
__device__ __forceinline__ void panel_factor(
    float* __restrict__ As, const int* __restrict__ rowoff,
    int* __restrict__ perm, int* __restrict__ s_prow,
    float* __restrict__ s_inv, float* __restrict__ s_piv,
    int kb, int lane)
{
    float a[4][8];
    #pragma unroll
    for (int r = 0; r < 4; r++) {
        const int off = rowoff[4 * lane + r] + kb;
        *(float4*)&a[r][0] = *(const float4*)&As[off];
        *(float4*)&a[r][4] = *(const float4*)&As[off + 4];
    }
    #pragma unroll
    for (int m = 0; m < NB; m++) {
        const int k = kb + m;
        unsigned key = 0u;
        #pragma unroll
        for (int r = 0; r < 4; r++) {
            const int row = 4 * lane + r;
            if (row >= k) {
                unsigned kk = (__float_as_uint(fabsf(a[r][m])) & 0xFFFFFF80u)
                              | (unsigned)row;
                key = max(key, kk);
            }
        }
        key = __reduce_max_sync(0xffffffffu, key);
        const int p  = (int)(key & 127u);
        const int tk = k >> 2, lk = k & 3;
        const int tp = p >> 2, lp = p & 3;

        float rowk[8], rowp[8];
        #pragma unroll
        for (int j = 0; j < 8; j++) {
            float vk = a[0][j];
            if (lk == 1) vk = a[1][j];
            if (lk == 2) vk = a[2][j];
            if (lk == 3) vk = a[3][j];
            rowk[j] = __shfl_sync(0xffffffffu, vk, tk);
            float vp = a[0][j];
            if (lp == 1) vp = a[1][j];
            if (lp == 2) vp = a[2][j];
            if (lp == 3) vp = a[3][j];
            rowp[j] = __shfl_sync(0xffffffffu, vp, tp);
        }
        const float pivot = rowp[m];
        const float inv   = 1.0f / pivot;

        #pragma unroll
        for (int r = 0; r < 4; r++) {
            const bool isk = (lane == tk) && (r == lk);
            const bool isp = (lane == tp) && (r == lp);
            #pragma unroll
            for (int j = 0; j < 8; j++) {
                if (isk)      a[r][j] = rowp[j];
                else if (isp) a[r][j] = rowk[j];
            }
        }
        if (lane == 0) {
            s_inv[m] = inv;
            s_piv[k] = pivot;
            if (p != k) { int t0 = perm[k]; perm[k] = perm[p]; perm[p] = t0; }
        }
        __syncwarp();

        float u[8];
        #pragma unroll
        for (int j = 0; j < 8; j++) u[j] = inv * rowp[j];
        #pragma unroll
        for (int r = 0; r < 4; r++) {
            const int row = 4 * lane + r;
            if (row > k) {
                const float mult = a[r][m];
                #pragma unroll
                for (int j = 0; j < 8; j++)
                    if (j > m) a[r][j] -= mult * u[j];
            }
        }
    }
    #pragma unroll
    for (int r = 0; r < 4; r++) {
        const int off = perm[4 * lane + r] * S + kb;
        *(float4*)&As[off]     = *(float4*)&a[r][0];
        *(float4*)&As[off + 4] = *(float4*)&a[r][4];
    }
    if (lane < NB) s_prow[lane] = perm[kb + lane] * S;
    __syncwarp();
}

__global__ __launch_bounds__(NTHREADS, 3)
void slater_logdet_kernel(const int* __restrict__ n_occ,
                          const float* __restrict__ M,
                          float* __restrict__ out)
{
    extern __shared__ float As[];            // NF * S floats
    __shared__ int   Rsh[NF];
    __shared__ int   warpCnt[8];
    __shared__ int   perm[NF];               // logical row -> physical row
    __shared__ int   rowoff[NF];             // perm snapshot * S
    __shared__ int   s_prow[2][NB];          // double-buffered panel row offsets
    __shared__ float s_inv[2][NB];           // double-buffered pivot reciprocals
    __shared__ float s_piv[NF];
    __shared__ float s_red[8];

    const int b    = blockIdx.x;
    const int tid  = threadIdx.x;
    const int lane = tid & 31;
    const int wid  = tid >> 5;

    // ---- Phase 1: occupied orbital indices, ascending (ballot + scan) ----
    int occ = (n_occ[b * N_ORB + tid] != 0);
    unsigned bm = __ballot_sync(0xffffffffu, occ);
    int rank = __popc(bm & ((1u << lane) - 1u));
    if (lane == 0) warpCnt[wid] = __popc(bm);
    if (tid < NF) { perm[tid] = tid; rowoff[tid] = tid * S; }
    __syncthreads();
    int base = 0;
    #pragma unroll
    for (int w = 0; w < 8; w++) if (w < wid) base += warpCnt[w];
    if (occ) Rsh[base + rank] = tid;
    __syncthreads();

    // ---- Phase 2: gather A[f][:] = M[R[f]][:]  (float4) ----
    const float4* M4 = (const float4*)M;
    #pragma unroll
    for (int t = 0; t < 16; t++) {
        int idx = tid + t * NTHREADS;
        int f = idx >> 5;
        int q = idx & 31;
        float4 v = M4[Rsh[f] * 32 + q];
        *(float4*)&As[f * S + 4 * q] = v;
    }
    __syncthreads();

    // ---- Phase 3: blocked LU with panel lookahead ----
    if (wid == 0)
        panel_factor(As, rowoff, perm, s_prow[0], s_inv[0], s_piv, 0, lane);
    __syncthreads();

    for (int kb = 0; kb < NF - NB; kb += NB) {
        const int c0    = kb + NB;
        const int buf   = (kb >> 3) & 1;
        const int nrows = NF - c0;

        // step 1: refresh rowoff (perm after panel kb) + trsm all trailing cols.
        // trsm: V = diag(inv) * L11^{-1} * A12, in place; L11 raw, reads broadcast.
        if (tid < NF) rowoff[tid] = perm[tid] * S;
        if (tid < nrows) {
            const int j = c0 + tid;
            float v[NB];
            #pragma unroll
            for (int m = 0; m < NB; m++) {
                float acc = As[s_prow[buf][m] + j];
                #pragma unroll
                for (int t2 = 0; t2 < m; t2++)
                    acc -= As[s_prow[buf][m] + kb + t2] * v[t2];
                v[m] = acc * s_inv[buf][m];
            }
            #pragma unroll
            for (int m = 0; m < NB; m++)
                As[s_prow[buf][m] + j] = v[m];
        }
        __syncthreads();

        // step 2: narrow GEMM — update ONLY next panel's columns [c0, c0+8).
        // thread = (row, col-half): 2*nrows threads, 1 row x 4 cols each.
        if (tid < 2 * nrows) {
            const int r  = c0 + (tid >> 1);
            const int j0 = c0 + 4 * (tid & 1);
            const int o  = rowoff[r];
            float l[8];
            *(float4*)&l[0] = *(const float4*)&As[o + kb];
            *(float4*)&l[4] = *(const float4*)&As[o + kb + 4];
            float acc[4];
            *(float4*)acc = *(const float4*)&As[o + j0];
            #pragma unroll
            for (int m = 0; m < NB; m++) {
                float u[4];
                *(float4*)u = *(const float4*)&As[s_prow[buf][m] + j0];
                #pragma unroll
                for (int c = 0; c < 4; c++) acc[c] -= l[m] * u[c];
            }
            *(float4*)&As[o + j0] = *(float4*)acc;
        }
        __syncthreads();

        // step 3 (concurrent): warp 0 factors the NEXT panel (cols now current),
        // warps 1..7 bulk-GEMM the remaining trailing columns with panel kb.
        if (wid == 0) {
            panel_factor(As, rowoff, perm, s_prow[buf ^ 1], s_inv[buf ^ 1],
                         s_piv, c0, lane);
        } else {
            const int ncols2 = nrows - NB;        // cols [c0+8, 128)
            if (ncols2 > 0) {
                const int nct = ncols2 >> 2;
                const int nrt = nrows  >> 2;
                if (lane < nct) {
                    const int j0 = c0 + NB + 4 * lane;
                    float uu[8][4];
                    #pragma unroll
                    for (int m = 0; m < NB; m++)
                        *(float4*)&uu[m][0] =
                            *(const float4*)&As[s_prow[buf][m] + j0];

                    for (int tr = wid - 1; tr < nrt; tr += 7) {
                        const int r0 = c0 + 4 * tr;
                        const int o0 = rowoff[r0],     o1 = rowoff[r0 + 1];
                        const int o2 = rowoff[r0 + 2], o3 = rowoff[r0 + 3];

                        float a0[4], a1[4], a2[4], a3[4];
                        *(float4*)a0 = *(const float4*)&As[o0 + j0];
                        *(float4*)a1 = *(const float4*)&As[o1 + j0];
                        *(float4*)a2 = *(const float4*)&As[o2 + j0];
                        *(float4*)a3 = *(const float4*)&As[o3 + j0];

                        #pragma unroll
                        for (int h = 0; h < 2; h++) {
                            float l0[4], l1[4], l2[4], l3[4];
                            *(float4*)l0 = *(const float4*)&As[o0 + kb + 4 * h];
                            *(float4*)l1 = *(const float4*)&As[o1 + kb + 4 * h];
                            *(float4*)l2 = *(const float4*)&As[o2 + kb + 4 * h];
                            *(float4*)l3 = *(const float4*)&As[o3 + kb + 4 * h];
                            #pragma unroll
                            for (int mm = 0; mm < 4; mm++) {
                                const int m = 4 * h + mm;
                                #pragma unroll
                                for (int c = 0; c < 4; c++) {
                                    a0[c] -= l0[mm] * uu[m][c];
                                    a1[c] -= l1[mm] * uu[m][c];
                                    a2[c] -= l2[mm] * uu[m][c];
                                    a3[c] -= l3[mm] * uu[m][c];
                                }
                            }
                        }
                        *(float4*)&As[o0 + j0] = *(float4*)a0;
                        *(float4*)&As[o1 + j0] = *(float4*)a1;
                        *(float4*)&As[o2 + j0] = *(float4*)a2;
                        *(float4*)&As[o3 + j0] = *(float4*)a3;
                    }
                }
            }
        }
        __syncthreads();
    }

    // ---- Phase 4: logabs = sum log|pivot| ----
    float lsum = 0.0f;
    if (tid < NF) lsum = logf(fabsf(s_piv[tid]));
    #pragma unroll
    for (int o = 16; o; o >>= 1) lsum += __shfl_down_sync(0xffffffffu, lsum, o);
    if (lane == 0) s_red[wid] = lsum;
    __syncthreads();
    if (tid == 0) {
        float tot = 0.0f;
        #pragma unroll
        for (int w = 0; w < 8; w++) tot += s_red[w];
        out[b] = tot;
    }
}

extern "C" void kernel_launch(void* const* d_in, const int* in_sizes, int n_in,
                              void* d_out, int out_size)
{
    (void)in_sizes; (void)n_in; (void)out_size;
    const int*   n_occ = (const int*)d_in[0];
    const float* M     = (const float*)d_in[1];
    float*       out   = (float*)d_out;

    const int smem = NF * S * (int)sizeof(float);   // 67584 bytes dynamic
    cudaFuncSetAttribute(slater_logdet_kernel,
                         cudaFuncAttributeMaxDynamicSharedMemorySize, smem);
    slater_logdet_kernel<<<BATCH, NTHREADS, smem>>>(n_occ, M, out);
}